// round 1
// baseline (speedup 1.0000x reference)
#include <cuda_runtime.h>
#include <math.h>
#include <limits.h>

#define NN 3000
#define EE 48000
#define K1 1500
#define K2 750

// ---------------- device memory pools (no cudaMalloc allowed) ----------------
static const size_t F_A1   = 0;                       // 1500*1500
static const size_t F_A2   = F_A1   + 2250000;        // 750*750
static const size_t F_R    = F_A2   + 562500;         // 750*1500
static const size_t F_G    = F_R    + 1125000;        // 1500*750
static const size_t F_D    = F_G    + 1125000;        // 750*750
static const size_t F_XW   = F_D    + 562500;         // 3000*64
static const size_t F_XS   = F_XW   + 192000;         // 3000*64
static const size_t F_AGG  = F_XS   + 192000;         // 3000*64
static const size_t F_H0   = F_AGG  + 192000;         // 3000*64 (res0)
static const size_t F_H1   = F_H0   + 192000;         // 1500*64 (res1)
static const size_t F_H2   = F_H1   + 96000;          // 750*64
static const size_t F_HP1  = F_H2   + 48000;          // 1500*64
static const size_t F_HP2  = F_HP1  + 96000;          // 750*64
static const size_t F_U1   = F_HP2  + 48000;          // 1500*64
static const size_t F_HUP  = F_U1   + 96000;          // 1500*64
static const size_t F_U0   = F_HUP  + 96000;          // 3000*64
static const size_t F_SC   = F_U0   + 192000;         // 3000
static const size_t F_DEG  = F_SC   + 3000;           // 3000
static const size_t F_DI0  = F_DEG  + 3000;           // 3000
static const size_t F_DI1  = F_DI0  + 3000;           // 1500
static const size_t F_DI2  = F_DI1  + 1500;           // 750
static const size_t F_PN   = F_DI2  + 750;            // 2 (pad)
static const size_t F_HWF  = F_PN   + 2;              // 3000*16
static const size_t F_AGGF = F_HWF  + 48000;          // 3000*16
static const size_t F_TOT  = F_AGGF + 48000;

__device__ float g_fpool[F_TOT];

static const size_t I_CNT    = 0;
static const size_t I_COLCNT = I_CNT    + 3000;
static const size_t I_FILL   = I_COLCNT + 3000;
static const size_t I_ROWPTR = I_FILL   + 3000;   // 3001
static const size_t I_COLS   = I_ROWPTR + 3004;   // 48000
static const size_t I_PERM1  = I_COLS   + 48000;  // 1500
static const size_t I_PERM2  = I_PERM1  + 1500;   // 750
static const size_t I_MAP1   = I_PERM2  + 750;    // 3000
static const size_t I_MAP2   = I_MAP1   + 3000;   // 1500
static const size_t I_TOT    = I_MAP2   + 1500;

__device__ int g_ipool[I_TOT];

// ---------------- kernels ----------------

__global__ void k_count(const int* __restrict__ ei, int* cnt, int* colcnt) {
    int e = blockIdx.x * blockDim.x + threadIdx.x;
    if (e >= EE) return;
    atomicAdd(&cnt[ei[e]], 1);
    atomicAdd(&colcnt[ei[EE + e]], 1);
}

__global__ void k_dinv0(const int* __restrict__ colcnt, float* dinv0) {
    int t = blockIdx.x * blockDim.x + threadIdx.x;
    if (t >= NN) return;
    dinv0[t] = rsqrtf((float)colcnt[t] + 2.0f);
}

__global__ void k_scan(const int* __restrict__ cnt, int* rowptr) {
    __shared__ int part[1024];
    int tid = threadIdx.x;
    int base = tid * 3;
    int l0, l1, l2, sum = 0, v;
    l0 = sum; v = (base + 0 < NN) ? cnt[base + 0] : 0; sum += v;
    l1 = sum; v = (base + 1 < NN) ? cnt[base + 1] : 0; sum += v;
    l2 = sum; v = (base + 2 < NN) ? cnt[base + 2] : 0; sum += v;
    part[tid] = sum;
    __syncthreads();
    for (int off = 1; off < 1024; off <<= 1) {
        int t = (tid >= off) ? part[tid - off] : 0;
        __syncthreads();
        part[tid] += t;
        __syncthreads();
    }
    int offset = (tid > 0) ? part[tid - 1] : 0;
    if (base + 0 < NN) rowptr[base + 0] = offset + l0;
    if (base + 1 < NN) rowptr[base + 1] = offset + l1;
    if (base + 2 < NN) rowptr[base + 2] = offset + l2;
    if (tid == 1023) rowptr[NN] = part[1023];
}

__global__ void k_fill(const int* __restrict__ ei, const int* __restrict__ rowptr,
                       int* fill, int* cols) {
    int e = blockIdx.x * blockDim.x + threadIdx.x;
    if (e >= EE) return;
    int s = ei[e];
    int p = rowptr[s] + atomicAdd(&fill[s], 1);
    cols[p] = ei[EE + e];
}

// Y[n,kout] = X[n,kin] @ W[kin,kout]
__global__ void k_linear(const float* __restrict__ X, const float* __restrict__ W,
                         float* __restrict__ Y, int n, int kin, int kout) {
    int idx = blockIdx.x * blockDim.x + threadIdx.x;
    if (idx >= n * kout) return;
    int i = idx / kout, c = idx - i * kout;
    const float* xr = X + (size_t)i * kin;
    float s = 0.f;
    for (int k = 0; k < kin; k++) s += xr[k] * W[k * kout + c];
    Y[idx] = s;
}

__global__ void k_scale(const float* __restrict__ X, const float* __restrict__ dinv,
                        float* __restrict__ Y, int n, int C) {
    int idx = blockIdx.x * blockDim.x + threadIdx.x;
    if (idx >= n * C) return;
    int i = idx / C;
    Y[idx] = X[idx] * dinv[i];
}

__global__ void k_edge_scatter(const int* __restrict__ ei, const float* __restrict__ xs,
                               float* agg, int C) {
    int idx = blockIdx.x * blockDim.x + threadIdx.x;
    if (idx >= EE * C) return;
    int e = idx / C, c = idx - e * C;
    int s = ei[e], t = ei[EE + e];
    atomicAdd(&agg[t * C + c], xs[s * C + c]);
}

__global__ void k_finalize(const float* __restrict__ agg, const float* __restrict__ hw,
                           const float* __restrict__ dinv, const float* __restrict__ b,
                           float* __restrict__ out, int n, int C, int act) {
    int idx = blockIdx.x * blockDim.x + threadIdx.x;
    if (idx >= n * C) return;
    int i = idx / C, c = idx - i * C;
    float di = dinv[i];
    float v = di * agg[idx] + 2.f * di * di * hw[idx] + b[c];
    out[idx] = act ? tanhf(v) : v;
}

__global__ void k_pnorm(const float* __restrict__ p, float* out) {
    __shared__ float sh[64];
    int tid = threadIdx.x;
    float v = p[tid];
    sh[tid] = v * v;
    __syncthreads();
    for (int off = 32; off > 0; off >>= 1) {
        if (tid < off) sh[tid] += sh[tid + off];
        __syncthreads();
    }
    if (tid == 0) out[0] = 1.0f / sqrtf(sh[0]);
}

__global__ void k_score(const float* __restrict__ h, const float* __restrict__ p,
                        const float* __restrict__ invn, float* score, int n) {
    int gtid = blockIdx.x * blockDim.x + threadIdx.x;
    int w = gtid >> 5, lane = gtid & 31;
    if (w >= n) return;
    const float* hr = h + (size_t)w * 64;
    float d = hr[lane] * p[lane] + hr[lane + 32] * p[lane + 32];
    #pragma unroll
    for (int off = 16; off > 0; off >>= 1) d += __shfl_down_sync(0xffffffffu, d, off);
    if (lane == 0) score[w] = tanhf(d * invn[0]);
}

#define SORT_N 4096
__global__ void k_topk(const float* __restrict__ score, int n, int k, int* perm) {
    __shared__ float key[SORT_N];
    __shared__ int   idx[SORT_N];
    int tid = threadIdx.x;
    float ninf = __int_as_float(0xff800000);
    for (int t = tid; t < SORT_N; t += 1024) {
        if (t < n) { key[t] = score[t]; idx[t] = t; }
        else       { key[t] = ninf;     idx[t] = INT_MAX; }
    }
    __syncthreads();
    for (int kk = 2; kk <= SORT_N; kk <<= 1) {
        for (int j = kk >> 1; j > 0; j >>= 1) {
            for (int t = tid; t < SORT_N; t += 1024) {
                int ixj = t ^ j;
                if (ixj > t) {
                    float ka = key[t], kb = key[ixj];
                    int ia = idx[t], ib = idx[ixj];
                    // "a before b" in descending order (ties -> lower index first)
                    bool aBeforeB = (ka > kb) || (ka == kb && ia < ib);
                    bool descBlock = ((t & kk) == 0);
                    bool doswap = descBlock ? (!aBeforeB) : aBeforeB;
                    if (doswap) { key[t] = kb; key[ixj] = ka; idx[t] = ib; idx[ixj] = ia; }
                }
            }
            __syncthreads();
        }
    }
    for (int t = tid; t < k; t += 1024) perm[t] = idx[t];
}

__global__ void k_setmap(const int* __restrict__ perm, int* map, int k) {
    int i = blockIdx.x * blockDim.x + threadIdx.x;
    if (i < k) map[perm[i]] = i;
}

__global__ void k_pool(const float* __restrict__ h, const float* __restrict__ score,
                       const int* __restrict__ perm, float* hp, int k) {
    int idx = blockIdx.x * blockDim.x + threadIdx.x;
    if (idx >= k * 64) return;
    int i = idx >> 6, c = idx & 63;
    int src = perm[i];
    hp[idx] = h[(size_t)src * 64 + c] * score[src];
}

// B@B contribution (B = offdiag(A0)) restricted to perm x perm, diag skipped
__global__ void k_bb(const int* __restrict__ ei, const int* __restrict__ rowptr,
                     const int* __restrict__ cols, const int* __restrict__ map,
                     float* Asub, int nsub) {
    int e = blockIdx.x * blockDim.x + threadIdx.x;
    if (e >= EE) return;
    int s = ei[e], t = ei[EE + e];
    if (s == t) return;
    int i = map[s];
    if (i < 0) return;
    int p0 = rowptr[t], p1 = rowptr[t + 1];
    for (int p = p0; p < p1; p++) {
        int u = cols[p];
        if (u == t) continue;
        int j = map[u];
        if (j < 0 || j == i) continue;
        atomicAdd(&Asub[(size_t)i * nsub + j], 1.0f);
    }
}

// 2B contribution
__global__ void k_b2(const int* __restrict__ ei, const int* __restrict__ map,
                     float* Asub, int nsub) {
    int e = blockIdx.x * blockDim.x + threadIdx.x;
    if (e >= EE) return;
    int s = ei[e], t = ei[EE + e];
    if (s == t) return;
    int i = map[s], j = map[t];
    if (i < 0 || j < 0) return;
    atomicAdd(&Asub[(size_t)i * nsub + j], 2.0f);
}

__global__ void k_fillf(float* p, float v, int n) {
    int idx = blockIdx.x * blockDim.x + threadIdx.x;
    if (idx < n) p[idx] = v;
}

__global__ void k_colsum(const float* __restrict__ A, float* deg, int n) {
    int t = blockIdx.x * blockDim.x + threadIdx.x;
    if (t >= n) return;
    int chunks = gridDim.y;
    int per = (n + chunks - 1) / chunks;
    int s0 = blockIdx.y * per;
    int s1 = min(s0 + per, n);
    float s = 0.f;
    for (int ss = s0; ss < s1; ss++) s += A[(size_t)ss * n + t];
    atomicAdd(&deg[t], s);
}

__global__ void k_rsqrt(const float* __restrict__ deg, float* dinv, int n) {
    int idx = blockIdx.x * blockDim.x + threadIdx.x;
    if (idx < n) dinv[idx] = rsqrtf(deg[idx]);
}

// out[t,c] += sum_s A[s,t] * X[s,c]   (X has 64 cols; out pre-zeroed; atomic s-split)
__global__ void k_atx(const float* __restrict__ A, const float* __restrict__ X,
                      float* out, int n) {
    __shared__ float As[8][32];
    __shared__ float Xs[8][64];
    int tid = threadIdx.x;                 // 256
    int c = tid & 63, g = tid >> 6;        // 64 cols x 4 groups
    int T0 = blockIdx.x * 32;
    int chunks = gridDim.y;
    int per = (n + chunks - 1) / chunks;
    int s_begin = blockIdx.y * per;
    int s_end = min(s_begin + per, n);
    float acc[8] = {0.f, 0.f, 0.f, 0.f, 0.f, 0.f, 0.f, 0.f};
    for (int s0 = s_begin; s0 < s_end; s0 += 8) {
        {
            int ss = tid >> 5, tt = tid & 31;
            int gs = s0 + ss, gt = T0 + tt;
            As[ss][tt] = (gs < s_end && gt < n) ? A[(size_t)gs * n + gt] : 0.f;
        }
        #pragma unroll
        for (int q = 0; q < 2; q++) {
            int li = tid + q * 256;
            int ss = li >> 6, cc = li & 63;
            int gs = s0 + ss;
            Xs[ss][cc] = (gs < s_end) ? X[(size_t)gs * 64 + cc] : 0.f;
        }
        __syncthreads();
        #pragma unroll
        for (int ss = 0; ss < 8; ss++) {
            float xv = Xs[ss][c];
            #pragma unroll
            for (int k = 0; k < 8; k++) acc[k] += As[ss][g * 8 + k] * xv;
        }
        __syncthreads();
    }
    #pragma unroll
    for (int k = 0; k < 8; k++) {
        int t = T0 + g * 8 + k;
        if (t < n) atomicAdd(&out[(size_t)t * 64 + c], acc[k]);
    }
}

__global__ void k_gather_rows(const float* __restrict__ A, const int* __restrict__ perm,
                              float* R, int nsub, int n) {
    int idx = blockIdx.x * blockDim.x + threadIdx.x;
    if (idx >= nsub * n) return;
    int i = idx / n, k = idx - i * n;
    R[idx] = A[(size_t)perm[i] * n + k];
}

__global__ void k_gather_cols(const float* __restrict__ A, const int* __restrict__ perm,
                              float* G, int n, int nsub) {
    int idx = blockIdx.x * blockDim.x + threadIdx.x;
    if (idx >= n * nsub) return;
    int k = idx / nsub, j = idx - k * nsub;
    G[idx] = A[(size_t)k * n + perm[j]];
}

// C[M,N] = A[M,K] @ B[K,N], 64x64 tile, kt=16, 256 threads, 4x4 per thread
__global__ void k_sgemm(const float* __restrict__ A, const float* __restrict__ B,
                        float* __restrict__ C, int M, int N, int K) {
    __shared__ float As[16][68];
    __shared__ float Bs[16][68];
    int tid = threadIdx.x;
    int tx = tid & 15, ty = tid >> 4;
    int row0 = blockIdx.y * 64, col0 = blockIdx.x * 64;
    float acc[4][4] = {};
    for (int k0 = 0; k0 < K; k0 += 16) {
        {
            int r = tid >> 2, kq = (tid & 3) * 4;
            int gr = row0 + r;
            #pragma unroll
            for (int q = 0; q < 4; q++) {
                int gk = k0 + kq + q;
                As[kq + q][r] = (gr < M && gk < K) ? A[(size_t)gr * K + gk] : 0.f;
            }
        }
        {
            int kk = tid >> 4, cq = (tid & 15) * 4;
            int gk = k0 + kk;
            #pragma unroll
            for (int q = 0; q < 4; q++) {
                int gc = col0 + cq + q;
                Bs[kk][cq + q] = (gk < K && gc < N) ? B[(size_t)gk * N + gc] : 0.f;
            }
        }
        __syncthreads();
        #pragma unroll
        for (int kk = 0; kk < 16; kk++) {
            float a[4], b[4];
            #pragma unroll
            for (int q = 0; q < 4; q++) a[q] = As[kk][ty * 4 + q];
            #pragma unroll
            for (int q = 0; q < 4; q++) b[q] = Bs[kk][tx * 4 + q];
            #pragma unroll
            for (int i = 0; i < 4; i++)
                #pragma unroll
                for (int j = 0; j < 4; j++) acc[i][j] += a[i] * b[j];
        }
        __syncthreads();
    }
    #pragma unroll
    for (int i = 0; i < 4; i++) {
        int gr = row0 + ty * 4 + i;
        if (gr >= M) continue;
        #pragma unroll
        for (int j = 0; j < 4; j++) {
            int gc = col0 + tx * 4 + j;
            if (gc < N) C[(size_t)gr * N + gc] = acc[i][j];
        }
    }
}

__global__ void k_buildA2(const float* __restrict__ D, const float* __restrict__ A1,
                          const int* __restrict__ perm, float* A2) {
    int idx = blockIdx.x * blockDim.x + threadIdx.x;
    if (idx >= K2 * K2) return;
    int i = idx / K2, j = idx - i * K2;
    A2[idx] = (i == j) ? 0.f
            : D[idx] + 2.0f * A1[(size_t)perm[i] * K1 + perm[j]];
}

__global__ void k_addup(const float* __restrict__ res, const float* __restrict__ hx,
                        const int* __restrict__ map, float* u, int n) {
    int idx = blockIdx.x * blockDim.x + threadIdx.x;
    if (idx >= n * 64) return;
    int t = idx >> 6, c = idx & 63;
    int m = map[t];
    u[idx] = res[idx] + (m >= 0 ? hx[(size_t)m * 64 + c] : 0.f);
}

// ---------------- host orchestration ----------------

extern "C" void kernel_launch(void* const* d_in, const int* in_sizes, int n_in,
                              void* d_out, int out_size) {
    float* fp = nullptr; int* ip = nullptr;
    cudaGetSymbolAddress((void**)&fp, g_fpool);
    cudaGetSymbolAddress((void**)&ip, g_ipool);

    const float* x   = (const float*)d_in[0];
    const int*   ei  = (const int*)  d_in[1];
    const float* W0  = (const float*)d_in[2];
    const float* b0  = (const float*)d_in[3];
    const float* W1  = (const float*)d_in[4];
    const float* b1  = (const float*)d_in[5];
    const float* W2  = (const float*)d_in[6];
    const float* b2  = (const float*)d_in[7];
    const float* p1  = (const float*)d_in[8];
    const float* p2  = (const float*)d_in[9];
    const float* Wu0 = (const float*)d_in[10];
    const float* bu0 = (const float*)d_in[11];
    const float* Wu1 = (const float*)d_in[12];
    const float* bu1 = (const float*)d_in[13];
    float* out = (float*)d_out;

    float *A1 = fp + F_A1, *A2 = fp + F_A2, *R = fp + F_R, *G = fp + F_G, *D = fp + F_D,
          *XW = fp + F_XW, *XS = fp + F_XS, *AGG = fp + F_AGG, *H0 = fp + F_H0,
          *H1 = fp + F_H1, *H2 = fp + F_H2, *HP1 = fp + F_HP1, *HP2 = fp + F_HP2,
          *U1 = fp + F_U1, *HUP = fp + F_HUP, *U0 = fp + F_U0, *SC = fp + F_SC,
          *DEG = fp + F_DEG, *DI0 = fp + F_DI0, *DI1 = fp + F_DI1, *DI2 = fp + F_DI2,
          *PN = fp + F_PN, *HWF = fp + F_HWF, *AGGF = fp + F_AGGF;
    int *CNT = ip + I_CNT, *COLCNT = ip + I_COLCNT, *FILL = ip + I_FILL,
        *ROWPTR = ip + I_ROWPTR, *COLS = ip + I_COLS, *PERM1 = ip + I_PERM1,
        *PERM2 = ip + I_PERM2, *MAP1 = ip + I_MAP1, *MAP2 = ip + I_MAP2;

    cudaStream_t s = 0;
    const int TB = 256;
    #define GR(n) (((n) + TB - 1) / TB)

    // ---- CSR of A0 + deg0 ----
    cudaMemsetAsync(CNT, 0, 3000 * 4, s);
    cudaMemsetAsync(COLCNT, 0, 3000 * 4, s);
    cudaMemsetAsync(FILL, 0, 3000 * 4, s);
    k_count<<<GR(EE), TB, 0, s>>>(ei, CNT, COLCNT);
    k_dinv0<<<GR(NN), TB, 0, s>>>(COLCNT, DI0);
    k_scan<<<1, 1024, 0, s>>>(CNT, ROWPTR);
    k_fill<<<GR(EE), TB, 0, s>>>(ei, ROWPTR, FILL, COLS);

    // ---- GCN0: h0 = tanh(gcn(x, A0, W0, b0)) ----
    k_linear<<<GR(NN * 64), TB, 0, s>>>(x, W0, XW, NN, 16, 64);
    k_scale<<<GR(NN * 64), TB, 0, s>>>(XW, DI0, XS, NN, 64);
    cudaMemsetAsync(AGG, 0, (size_t)NN * 64 * 4, s);
    k_edge_scatter<<<GR(EE * 64), TB, 0, s>>>(ei, XS, AGG, 64);
    k_finalize<<<GR(NN * 64), TB, 0, s>>>(AGG, XW, DI0, b0, H0, NN, 64, 1);

    // ---- pool 1 ----
    k_pnorm<<<1, 64, 0, s>>>(p1, PN);
    k_score<<<GR(NN * 32), TB, 0, s>>>(H0, p1, PN, SC, NN);
    k_topk<<<1, 1024, 0, s>>>(SC, NN, K1, PERM1);
    cudaMemsetAsync(MAP1, 0xFF, 3000 * 4, s);
    k_setmap<<<GR(K1), TB, 0, s>>>(PERM1, MAP1, K1);
    k_pool<<<GR(K1 * 64), TB, 0, s>>>(H0, SC, PERM1, HP1, K1);

    // ---- A1 = augment(A0)[perm1, perm1] via sparse two-hop ----
    cudaMemsetAsync(A1, 0, (size_t)K1 * K1 * 4, s);
    k_bb<<<GR(EE), TB, 0, s>>>(ei, ROWPTR, COLS, MAP1, A1, K1);
    k_b2<<<GR(EE), TB, 0, s>>>(ei, MAP1, A1, K1);
    k_fillf<<<GR(K1), TB, 0, s>>>(DEG, 2.0f, K1);
    { dim3 g(GR(K1), 8); k_colsum<<<g, TB, 0, s>>>(A1, DEG, K1); }
    k_rsqrt<<<GR(K1), TB, 0, s>>>(DEG, DI1, K1);

    // ---- GCN1 ----
    k_linear<<<GR(K1 * 64), TB, 0, s>>>(HP1, W1, XW, K1, 64, 64);
    k_scale<<<GR(K1 * 64), TB, 0, s>>>(XW, DI1, XS, K1, 64);
    cudaMemsetAsync(AGG, 0, (size_t)K1 * 64 * 4, s);
    { dim3 g((K1 + 31) / 32, 8); k_atx<<<g, TB, 0, s>>>(A1, XS, AGG, K1); }
    k_finalize<<<GR(K1 * 64), TB, 0, s>>>(AGG, XW, DI1, b1, H1, K1, 64, 1);

    // ---- pool 2 ----
    k_pnorm<<<1, 64, 0, s>>>(p2, PN);
    k_score<<<GR(K1 * 32), TB, 0, s>>>(H1, p2, PN, SC, K1);
    k_topk<<<1, 1024, 0, s>>>(SC, K1, K2, PERM2);
    cudaMemsetAsync(MAP2, 0xFF, K1 * 4, s);
    k_setmap<<<GR(K2), TB, 0, s>>>(PERM2, MAP2, K2);
    k_pool<<<GR(K2 * 64), TB, 0, s>>>(H1, SC, PERM2, HP2, K2);

    // ---- A2 = augment(A1)[perm2, perm2] via dense GEMM ----
    k_gather_rows<<<GR(K2 * K1), TB, 0, s>>>(A1, PERM2, R, K2, K1);
    k_gather_cols<<<GR(K1 * K2), TB, 0, s>>>(A1, PERM2, G, K1, K2);
    { dim3 g((K2 + 63) / 64, (K2 + 63) / 64); k_sgemm<<<g, TB, 0, s>>>(R, G, D, K2, K2, K1); }
    k_buildA2<<<GR(K2 * K2), TB, 0, s>>>(D, A1, PERM2, A2);
    k_fillf<<<GR(K2), TB, 0, s>>>(DEG, 2.0f, K2);
    { dim3 g(GR(K2), 8); k_colsum<<<g, TB, 0, s>>>(A2, DEG, K2); }
    k_rsqrt<<<GR(K2), TB, 0, s>>>(DEG, DI2, K2);

    // ---- GCN2 ----
    k_linear<<<GR(K2 * 64), TB, 0, s>>>(HP2, W2, XW, K2, 64, 64);
    k_scale<<<GR(K2 * 64), TB, 0, s>>>(XW, DI2, XS, K2, 64);
    cudaMemsetAsync(AGG, 0, (size_t)K2 * 64 * 4, s);
    { dim3 g((K2 + 31) / 32, 8); k_atx<<<g, TB, 0, s>>>(A2, XS, AGG, K2); }
    k_finalize<<<GR(K2 * 64), TB, 0, s>>>(AGG, XW, DI2, b2, H2, K2, 64, 1);

    // ---- up to level 1 ----
    k_addup<<<GR(K1 * 64), TB, 0, s>>>(H1, H2, MAP2, U1, K1);
    k_linear<<<GR(K1 * 64), TB, 0, s>>>(U1, Wu0, XW, K1, 64, 64);
    k_scale<<<GR(K1 * 64), TB, 0, s>>>(XW, DI1, XS, K1, 64);
    cudaMemsetAsync(AGG, 0, (size_t)K1 * 64 * 4, s);
    { dim3 g((K1 + 31) / 32, 8); k_atx<<<g, TB, 0, s>>>(A1, XS, AGG, K1); }
    k_finalize<<<GR(K1 * 64), TB, 0, s>>>(AGG, XW, DI1, bu0, HUP, K1, 64, 1);

    // ---- up to level 0 (final, no activation) ----
    k_addup<<<GR(NN * 64), TB, 0, s>>>(H0, HUP, MAP1, U0, NN);
    k_linear<<<GR(NN * 16), TB, 0, s>>>(U0, Wu1, HWF, NN, 64, 16);
    k_scale<<<GR(NN * 16), TB, 0, s>>>(HWF, DI0, XS, NN, 16);
    cudaMemsetAsync(AGGF, 0, (size_t)NN * 16 * 4, s);
    k_edge_scatter<<<GR(EE * 16), TB, 0, s>>>(ei, XS, AGGF, 16);
    k_finalize<<<GR(NN * 16), TB, 0, s>>>(AGGF, HWF, DI0, bu1, out, NN, 16, 0);

    #undef GR
}

// round 2
// speedup vs baseline: 1.1813x; 1.1813x over previous
#include <cuda_runtime.h>
#include <math.h>
#include <limits.h>

#define NN 3000
#define EE 48000
#define K1 1500
#define K2 750

// ---------------- device memory pools (no cudaMalloc allowed) ----------------
// Zeroed-every-replay region (one memset): A1, AGG0..3, AGGF, DEG1, DEG2
static const size_t Z_A1   = 0;                      // 1500*1500
static const size_t Z_AGG0 = Z_A1   + 2250000;       // 3000*64
static const size_t Z_AGG1 = Z_AGG0 + 192000;        // 1500*64
static const size_t Z_AGG2 = Z_AGG1 + 96000;         // 750*64
static const size_t Z_AGG3 = Z_AGG2 + 48000;         // 1500*64
static const size_t Z_AGGF = Z_AGG3 + 96000;         // 3000*16
static const size_t Z_DEG1 = Z_AGGF + 48000;         // 1504
static const size_t Z_DEG2 = Z_DEG1 + 1504;          // 752
static const size_t ZTOT   = Z_DEG2 + 752;
// Non-zeroed scratch
static const size_t F_G    = ZTOT;                   // 1500*750
static const size_t F_A2   = F_G    + 1125000;       // 750*750
static const size_t F_XW   = F_A2   + 562500;        // 3000*64
static const size_t F_XS   = F_XW   + 192000;        // 3000*64
static const size_t F_H0   = F_XS   + 192000;        // 3000*64
static const size_t F_H1   = F_H0   + 192000;        // 1500*64
static const size_t F_H2   = F_H1   + 96000;         // 750*64
static const size_t F_HUP  = F_H2   + 48000;         // 1500*64
static const size_t F_SC   = F_HUP  + 96000;         // 3008
static const size_t F_TOT  = F_SC   + 3008;

__device__ float g_fpool[F_TOT];

// int pool; first IZTOT zeroed each replay
static const size_t IZ_CNT    = 0;                   // 3000
static const size_t IZ_COLCNT = 3000;                // 3000
static const size_t IZ_FILL   = 6000;                // 3000
static const size_t IZTOT     = 9000;
static const size_t I_ROWPTR  = 9000;                // 3004
static const size_t I_COLS    = I_ROWPTR + 3004;     // 48000
static const size_t I_PERM1   = I_COLS   + 48000;    // 1504
static const size_t I_PERM2   = I_PERM1  + 1504;     // 752
static const size_t I_MAP1    = I_PERM2  + 752;      // 3000
static const size_t I_MAP2    = I_MAP1   + 3000;     // 1504
static const size_t I_TOT     = I_MAP2   + 1504;

__device__ int g_ipool[I_TOT];

// ---------------- kernels ----------------

__global__ void k_count(const int* __restrict__ ei, int* cnt, int* colcnt) {
    int e = blockIdx.x * blockDim.x + threadIdx.x;
    if (e >= EE) return;
    atomicAdd(&cnt[ei[e]], 1);
    atomicAdd(&colcnt[ei[EE + e]], 1);
}

__global__ void k_scan(const int* __restrict__ cnt, int* rowptr) {
    __shared__ int part[1024];
    int tid = threadIdx.x;
    int base = tid * 3;
    int l0, l1, l2, sum = 0, v;
    l0 = sum; v = (base + 0 < NN) ? cnt[base + 0] : 0; sum += v;
    l1 = sum; v = (base + 1 < NN) ? cnt[base + 1] : 0; sum += v;
    l2 = sum; v = (base + 2 < NN) ? cnt[base + 2] : 0; sum += v;
    part[tid] = sum;
    __syncthreads();
    for (int off = 1; off < 1024; off <<= 1) {
        int t = (tid >= off) ? part[tid - off] : 0;
        __syncthreads();
        part[tid] += t;
        __syncthreads();
    }
    int offset = (tid > 0) ? part[tid - 1] : 0;
    if (base + 0 < NN) rowptr[base + 0] = offset + l0;
    if (base + 1 < NN) rowptr[base + 1] = offset + l1;
    if (base + 2 < NN) rowptr[base + 2] = offset + l2;
    if (tid == 1023) rowptr[NN] = part[1023];
}

__global__ void k_fill(const int* __restrict__ ei, const int* __restrict__ rowptr,
                       int* fill, int* cols) {
    int e = blockIdx.x * blockDim.x + threadIdx.x;
    if (e >= EE) return;
    int s = ei[e];
    int p = rowptr[s] + atomicAdd(&fill[s], 1);
    cols[p] = ei[EE + e];
}

// XW = x(NN x 16) @ W0(16 x 64); XS = XW * rsqrt(colcnt+2)
__global__ void k_lin0(const float* __restrict__ x, const float* __restrict__ W,
                       const int* __restrict__ colcnt, float* __restrict__ XW,
                       float* __restrict__ XS) {
    __shared__ float sh[4][16];
    int tid = threadIdx.x;
    int base = blockIdx.x * 4;
    if (tid < 64) {
        int r = tid >> 4, k = tid & 15;
        int i = base + r;
        sh[r][k] = (i < NN) ? x[i * 16 + k] : 0.f;
    }
    __syncthreads();
    int r = tid >> 6, c = tid & 63;
    int i = base + r;
    if (i >= NN) return;
    float acc = 0.f;
    #pragma unroll
    for (int k = 0; k < 16; k++) acc += sh[r][k] * W[k * 64 + c];
    float di = rsqrtf((float)colcnt[i] + 2.f);
    XW[i * 64 + c] = acc;
    XS[i * 64 + c] = acc * di;
}

// pooled linear: XW = (H[perm[i]] * sc[perm[i]]) @ W(64x64); XS = XW * rsqrt(deg[i]+2)
__global__ void k_linpool(const float* __restrict__ H, const float* __restrict__ sc,
                          const int* __restrict__ perm, const float* __restrict__ W,
                          const float* __restrict__ deg, float* __restrict__ XW,
                          float* __restrict__ XS, int n) {
    __shared__ float sh[4][64];
    int tid = threadIdx.x;
    int base = blockIdx.x * 4;
    int r = tid >> 6, kc = tid & 63;
    int i = base + r;
    float lv = 0.f;
    if (i < n) { int src = perm[i]; lv = H[(size_t)src * 64 + kc] * sc[src]; }
    sh[r][kc] = lv;
    __syncthreads();
    if (i >= n) return;
    float acc = 0.f;
    #pragma unroll
    for (int k = 0; k < 64; k++) acc += sh[r][k] * W[k * 64 + kc];
    float di = rsqrtf(deg[i] + 2.f);
    XW[i * 64 + kc] = acc;
    XS[i * 64 + kc] = acc * di;
}

// up-path linear: XW = (res + up[map]) @ W(64x64); XS = XW * rsqrt(deg+2)
__global__ void k_linup64(const float* __restrict__ res, const float* __restrict__ up,
                          const int* __restrict__ map, const float* __restrict__ W,
                          const float* __restrict__ deg, float* __restrict__ XW,
                          float* __restrict__ XS, int n) {
    __shared__ float sh[4][64];
    int tid = threadIdx.x;
    int base = blockIdx.x * 4;
    int r = tid >> 6, kc = tid & 63;
    int i = base + r;
    float lv = 0.f;
    if (i < n) {
        int m = map[i];
        lv = res[(size_t)i * 64 + kc] + (m >= 0 ? up[(size_t)m * 64 + kc] : 0.f);
    }
    sh[r][kc] = lv;
    __syncthreads();
    if (i >= n) return;
    float acc = 0.f;
    #pragma unroll
    for (int k = 0; k < 64; k++) acc += sh[r][k] * W[k * 64 + kc];
    float di = rsqrtf(deg[i] + 2.f);
    XW[i * 64 + kc] = acc;
    XS[i * 64 + kc] = acc * di;
}

// final up: XW(16) = (H0 + HUP[map1]) @ Wu1(64x16); XS = XW * rsqrt(colcnt+2)
__global__ void k_linup16(const float* __restrict__ res, const float* __restrict__ up,
                          const int* __restrict__ map, const float* __restrict__ W,
                          const int* __restrict__ colcnt, float* __restrict__ XW,
                          float* __restrict__ XS) {
    __shared__ float sh[16][64];
    int tid = threadIdx.x;
    int base = blockIdx.x * 16;
    #pragma unroll
    for (int q = 0; q < 4; q++) {
        int li = tid + q * 256;
        int r = li >> 6, k = li & 63;
        int i = base + r;
        float lv = 0.f;
        if (i < NN) {
            int m = map[i];
            lv = res[(size_t)i * 64 + k] + (m >= 0 ? up[(size_t)m * 64 + k] : 0.f);
        }
        sh[r][k] = lv;
    }
    __syncthreads();
    int r = tid >> 4, c = tid & 15;
    int i = base + r;
    if (i >= NN) return;
    float acc = 0.f;
    #pragma unroll
    for (int k = 0; k < 64; k++) acc += sh[r][k] * W[k * 16 + c];
    float di = rsqrtf((float)colcnt[i] + 2.f);
    XW[i * 16 + c] = acc;
    XS[i * 16 + c] = acc * di;
}

// vectorized edge scatter: Cq = C/4 float4 chunks per edge
__global__ void k_scatter4(const int* __restrict__ ei, const float* __restrict__ xs,
                           float* agg, int Cq) {
    int idx = blockIdx.x * blockDim.x + threadIdx.x;
    if (idx >= EE * Cq) return;
    int e = idx / Cq, q = idx - e * Cq;
    int s = ei[e], t = ei[EE + e];
    float4 v = reinterpret_cast<const float4*>(xs)[(size_t)s * Cq + q];
    float* d = &agg[((size_t)t * Cq + q) * 4];
    atomicAdd(d + 0, v.x);
    atomicAdd(d + 1, v.y);
    atomicAdd(d + 2, v.z);
    atomicAdd(d + 3, v.w);
}

// finalize (C=64) + optional topk-score (fused p-norm)
__global__ void k_fin_score(const float* __restrict__ agg, const float* __restrict__ xw,
                            const float* __restrict__ degf, const int* __restrict__ cnti,
                            const float* __restrict__ b, float* __restrict__ out, int n,
                            int act, const float* __restrict__ p, float* score) {
    __shared__ float part[8], ppart[8];
    int tid = threadIdx.x;
    int r = tid >> 6, c = tid & 63;
    int i = blockIdx.x * 4 + r;
    float v = 0.f;
    if (i < n) {
        float deg = degf ? degf[i] + 2.f : (float)cnti[i] + 2.f;
        float di = rsqrtf(deg);
        int idx = i * 64 + c;
        v = di * agg[idx] + 2.f * di * di * xw[idx] + b[c];
        if (act) v = tanhf(v);
        out[idx] = v;
    }
    if (p) {
        float pc = p[c];
        float hp = (i < n) ? v * pc : 0.f;
        float pp = (r == 0) ? pc * pc : 0.f;
        #pragma unroll
        for (int off = 16; off > 0; off >>= 1) {
            hp += __shfl_down_sync(0xffffffffu, hp, off);
            pp += __shfl_down_sync(0xffffffffu, pp, off);
        }
        int w = tid >> 5, lane = tid & 31;
        if (lane == 0) { part[w] = hp; ppart[w] = pp; }
        __syncthreads();
        if (tid < 4) {
            int ii = blockIdx.x * 4 + tid;
            if (ii < n) {
                float dot = part[tid * 2] + part[tid * 2 + 1];
                float pn = ppart[0] + ppart[1];
                score[ii] = tanhf(dot * rsqrtf(pn));
            }
        }
    }
}

// final finalize, C=16, no activation
__global__ void k_fin16(const float* __restrict__ agg, const float* __restrict__ xw,
                        const int* __restrict__ cnti, const float* __restrict__ b,
                        float* __restrict__ out) {
    int tid = threadIdx.x;
    int r = tid >> 4, c = tid & 15;
    int i = blockIdx.x * 16 + r;
    if (i >= NN) return;
    float di = rsqrtf((float)cnti[i] + 2.f);
    int idx = i * 16 + c;
    out[idx] = di * agg[idx] + 2.f * di * di * xw[idx] + b[c];
}

#define SORT_N 4096
__global__ void k_topk(const float* __restrict__ score, int n, int k,
                       int* perm, int* map) {
    __shared__ float key[SORT_N];
    __shared__ int   idx[SORT_N];
    int tid = threadIdx.x;
    float ninf = __int_as_float(0xff800000);
    for (int t = tid; t < SORT_N; t += 1024) {
        if (t < n) { key[t] = score[t]; idx[t] = t; }
        else       { key[t] = ninf;     idx[t] = INT_MAX; }
    }
    __syncthreads();
    for (int kk = 2; kk <= SORT_N; kk <<= 1) {
        for (int j = kk >> 1; j > 0; j >>= 1) {
            for (int t = tid; t < SORT_N; t += 1024) {
                int ixj = t ^ j;
                if (ixj > t) {
                    float ka = key[t], kb = key[ixj];
                    int ia = idx[t], ib = idx[ixj];
                    bool aBeforeB = (ka > kb) || (ka == kb && ia < ib);
                    bool descBlock = ((t & kk) == 0);
                    bool doswap = descBlock ? (!aBeforeB) : aBeforeB;
                    if (doswap) { key[t] = kb; key[ixj] = ka; idx[t] = ib; idx[ixj] = ia; }
                }
            }
            __syncthreads();
        }
    }
    for (int t = tid; t < SORT_N; t += 1024) {
        int id = idx[t];
        if (id < n) map[id] = (t < k) ? t : -1;
        if (t < k) perm[t] = id;
    }
}

// fused (B@B + 2B) restricted to perm x perm, diag skipped (B = offdiag(A0))
__global__ void k_bb2(const int* __restrict__ ei, const int* __restrict__ rowptr,
                      const int* __restrict__ cols, const int* __restrict__ map,
                      float* Asub, int nsub) {
    int e = blockIdx.x * blockDim.x + threadIdx.x;
    if (e >= EE) return;
    int s = ei[e], t = ei[EE + e];
    if (s == t) return;
    int i = map[s];
    if (i < 0) return;
    int j0 = map[t];
    if (j0 >= 0 && j0 != i) atomicAdd(&Asub[(size_t)i * nsub + j0], 2.0f);  // 2B term
    int p0 = rowptr[t], p1 = rowptr[t + 1];
    for (int p = p0; p < p1; p++) {
        int u = cols[p];
        if (u == t) continue;
        int j = map[u];
        if (j < 0 || j == i) continue;
        atomicAdd(&Asub[(size_t)i * nsub + j], 1.0f);                       // B@B term
    }
}

// partial column sums -> deg (deg pre-zeroed; +2 bias applied at consumers)
__global__ void k_colsum(const float* __restrict__ A, float* deg, int n) {
    int t = blockIdx.x * blockDim.x + threadIdx.x;
    if (t >= n) return;
    int chunks = gridDim.y;
    int per = (n + chunks - 1) / chunks;
    int s0 = blockIdx.y * per;
    int s1 = min(s0 + per, n);
    float s = 0.f;
    for (int ss = s0; ss < s1; ss++) s += A[(size_t)ss * n + t];
    atomicAdd(&deg[t], s);
}

// out[t,c] += sum_s A[s,t] * X[s,c]   (64 cols; out pre-zeroed; atomic s-split)
__global__ void k_atx(const float* __restrict__ A, const float* __restrict__ X,
                      float* out, int n) {
    __shared__ float As[8][32];
    __shared__ float Xs[8][64];
    int tid = threadIdx.x;
    int c = tid & 63, g = tid >> 6;
    int T0 = blockIdx.x * 32;
    int chunks = gridDim.y;
    int per = (n + chunks - 1) / chunks;
    int s_begin = blockIdx.y * per;
    int s_end = min(s_begin + per, n);
    float acc[8] = {0.f, 0.f, 0.f, 0.f, 0.f, 0.f, 0.f, 0.f};
    for (int s0 = s_begin; s0 < s_end; s0 += 8) {
        {
            int ss = tid >> 5, tt = tid & 31;
            int gs = s0 + ss, gt = T0 + tt;
            As[ss][tt] = (gs < s_end && gt < n) ? A[(size_t)gs * n + gt] : 0.f;
        }
        #pragma unroll
        for (int q = 0; q < 2; q++) {
            int li = tid + q * 256;
            int ss = li >> 6, cc = li & 63;
            int gs = s0 + ss;
            Xs[ss][cc] = (gs < s_end) ? X[(size_t)gs * 64 + cc] : 0.f;
        }
        __syncthreads();
        #pragma unroll
        for (int ss = 0; ss < 8; ss++) {
            float xv = Xs[ss][c];
            #pragma unroll
            for (int k = 0; k < 8; k++) acc[k] += As[ss][g * 8 + k] * xv;
        }
        __syncthreads();
    }
    #pragma unroll
    for (int k = 0; k < 8; k++) {
        int t = T0 + g * 8 + k;
        if (t < n) atomicAdd(&out[(size_t)t * 64 + c], acc[k]);
    }
}

// G[k, j] = A1[k, perm2[j]]  (coalesce B-side of A2 GEMM; reused 12x)
__global__ void k_gatherG(const float* __restrict__ A1, const int* __restrict__ perm,
                          float* __restrict__ G) {
    int idx = blockIdx.x * blockDim.x + threadIdx.x;
    if (idx >= K1 * K2) return;
    int k = idx / K2, j = idx - k * K2;
    G[idx] = A1[(size_t)k * K1 + perm[j]];
}

// A2 = (A1[perm,:] @ G) + 2*A1[perm_i, perm_j], diag 0; also column degree partials
__global__ void k_sgemmA2(const float* __restrict__ A1, const float* __restrict__ G,
                          const int* __restrict__ perm, float* __restrict__ A2,
                          float* deg2) {
    __shared__ float As[16][68];
    __shared__ float Bs[16][68];
    __shared__ int prs[64], pcs[64];
    __shared__ float csum[64];
    int tid = threadIdx.x;
    int tx = tid & 15, ty = tid >> 4;
    int row0 = blockIdx.y * 64, col0 = blockIdx.x * 64;
    if (tid < 64) {
        prs[tid] = (row0 + tid < K2) ? perm[row0 + tid] : 0;
        csum[tid] = 0.f;
    } else if (tid < 128) {
        int c = tid - 64;
        pcs[c] = (col0 + c < K2) ? perm[col0 + c] : 0;
    }
    __syncthreads();
    float acc[4][4] = {};
    for (int k0 = 0; k0 < K1; k0 += 16) {
        {
            int r = tid >> 2, kq = (tid & 3) * 4;
            bool vr = (row0 + r) < K2;
            int arow = prs[r];
            #pragma unroll
            for (int q = 0; q < 4; q++) {
                int gk = k0 + kq + q;
                As[kq + q][r] = (vr && gk < K1) ? A1[(size_t)arow * K1 + gk] : 0.f;
            }
        }
        {
            int kk = tid >> 4, cq = (tid & 15) * 4;
            int gk = k0 + kk;
            #pragma unroll
            for (int q = 0; q < 4; q++) {
                int gc = col0 + cq + q;
                Bs[kk][cq + q] = (gk < K1 && gc < K2) ? G[(size_t)gk * K2 + gc] : 0.f;
            }
        }
        __syncthreads();
        #pragma unroll
        for (int kk = 0; kk < 16; kk++) {
            float a[4], b[4];
            #pragma unroll
            for (int q = 0; q < 4; q++) a[q] = As[kk][ty * 4 + q];
            #pragma unroll
            for (int q = 0; q < 4; q++) b[q] = Bs[kk][tx * 4 + q];
            #pragma unroll
            for (int i = 0; i < 4; i++)
                #pragma unroll
                for (int j = 0; j < 4; j++) acc[i][j] += a[i] * b[j];
        }
        __syncthreads();
    }
    float cj[4] = {0.f, 0.f, 0.f, 0.f};
    #pragma unroll
    for (int i2 = 0; i2 < 4; i2++) {
        int gr = row0 + ty * 4 + i2;
        if (gr >= K2) continue;
        int ar = prs[ty * 4 + i2];
        #pragma unroll
        for (int j = 0; j < 4; j++) {
            int gc = col0 + tx * 4 + j;
            if (gc >= K2) continue;
            float val = (gr == gc) ? 0.f
                      : acc[i2][j] + 2.f * A1[(size_t)ar * K1 + pcs[tx * 4 + j]];
            A2[(size_t)gr * K2 + gc] = val;
            cj[j] += val;
        }
    }
    #pragma unroll
    for (int j = 0; j < 4; j++) atomicAdd(&csum[tx * 4 + j], cj[j]);
    __syncthreads();
    if (tid < 64 && col0 + tid < K2) atomicAdd(&deg2[col0 + tid], csum[tid]);
}

// ---------------- host orchestration ----------------

extern "C" void kernel_launch(void* const* d_in, const int* in_sizes, int n_in,
                              void* d_out, int out_size) {
    float* fp = nullptr; int* ip = nullptr;
    cudaGetSymbolAddress((void**)&fp, g_fpool);
    cudaGetSymbolAddress((void**)&ip, g_ipool);

    const float* x   = (const float*)d_in[0];
    const int*   ei  = (const int*)  d_in[1];
    const float* W0  = (const float*)d_in[2];
    const float* b0  = (const float*)d_in[3];
    const float* W1  = (const float*)d_in[4];
    const float* b1  = (const float*)d_in[5];
    const float* W2  = (const float*)d_in[6];
    const float* b2  = (const float*)d_in[7];
    const float* p1  = (const float*)d_in[8];
    const float* p2  = (const float*)d_in[9];
    const float* Wu0 = (const float*)d_in[10];
    const float* bu0 = (const float*)d_in[11];
    const float* Wu1 = (const float*)d_in[12];
    const float* bu1 = (const float*)d_in[13];
    float* out = (float*)d_out;

    float *A1 = fp + Z_A1, *AGG0 = fp + Z_AGG0, *AGG1 = fp + Z_AGG1,
          *AGG2 = fp + Z_AGG2, *AGG3 = fp + Z_AGG3, *AGGF = fp + Z_AGGF,
          *DEG1 = fp + Z_DEG1, *DEG2 = fp + Z_DEG2,
          *G = fp + F_G, *A2 = fp + F_A2, *XW = fp + F_XW, *XS = fp + F_XS,
          *H0 = fp + F_H0, *H1 = fp + F_H1, *H2 = fp + F_H2, *HUP = fp + F_HUP,
          *SC = fp + F_SC;
    int *CNT = ip + IZ_CNT, *COLCNT = ip + IZ_COLCNT, *FILL = ip + IZ_FILL,
        *ROWPTR = ip + I_ROWPTR, *COLS = ip + I_COLS, *PERM1 = ip + I_PERM1,
        *PERM2 = ip + I_PERM2, *MAP1 = ip + I_MAP1, *MAP2 = ip + I_MAP2;

    cudaStream_t s = 0;
    const int TB = 256;
    #define GR(n)  (((n) + TB - 1) / TB)
    #define GR4(n) (((n) + 3) / 4)

    // one memset per pool (all atomic-accumulated buffers are contiguous)
    cudaMemsetAsync(fp, 0, ZTOT * sizeof(float), s);
    cudaMemsetAsync(ip, 0, IZTOT * sizeof(int), s);

    // CSR + degrees of A0
    k_count<<<GR(EE), TB, 0, s>>>(ei, CNT, COLCNT);
    k_scan<<<1, 1024, 0, s>>>(CNT, ROWPTR);
    k_fill<<<GR(EE), TB, 0, s>>>(ei, ROWPTR, FILL, COLS);

    // GCN0 + score1
    k_lin0<<<GR4(NN), TB, 0, s>>>(x, W0, COLCNT, XW, XS);
    k_scatter4<<<GR(EE * 16), TB, 0, s>>>(ei, XS, AGG0, 16);
    k_fin_score<<<GR4(NN), TB, 0, s>>>(AGG0, XW, nullptr, COLCNT, b0, H0, NN, 1, p1, SC);

    // pool 1 + A1
    k_topk<<<1, 1024, 0, s>>>(SC, NN, K1, PERM1, MAP1);
    k_bb2<<<GR(EE), TB, 0, s>>>(ei, ROWPTR, COLS, MAP1, A1, K1);
    { dim3 g(GR(K1), 32); k_colsum<<<g, TB, 0, s>>>(A1, DEG1, K1); }

    // GCN1 + score2
    k_linpool<<<GR4(K1), TB, 0, s>>>(H0, SC, PERM1, W1, DEG1, XW, XS, K1);
    { dim3 g((K1 + 31) / 32, 8); k_atx<<<g, TB, 0, s>>>(A1, XS, AGG1, K1); }
    k_fin_score<<<GR4(K1), TB, 0, s>>>(AGG1, XW, DEG1, nullptr, b1, H1, K1, 1, p2, SC);

    // pool 2 + A2 (GEMM with fused gathers/epilogue/deg)
    k_topk<<<1, 1024, 0, s>>>(SC, K1, K2, PERM2, MAP2);
    k_gatherG<<<GR(K1 * K2), TB, 0, s>>>(A1, PERM2, G);
    { dim3 g(12, 12); k_sgemmA2<<<g, TB, 0, s>>>(A1, G, PERM2, A2, DEG2); }

    // GCN2
    k_linpool<<<GR4(K2), TB, 0, s>>>(H1, SC, PERM2, W2, DEG2, XW, XS, K2);
    { dim3 g((K2 + 31) / 32, 8); k_atx<<<g, TB, 0, s>>>(A2, XS, AGG2, K2); }
    k_fin_score<<<GR4(K2), TB, 0, s>>>(AGG2, XW, DEG2, nullptr, b2, H2, K2, 1, nullptr, nullptr);

    // up to level 1
    k_linup64<<<GR4(K1), TB, 0, s>>>(H1, H2, MAP2, Wu0, DEG1, XW, XS, K1);
    { dim3 g((K1 + 31) / 32, 8); k_atx<<<g, TB, 0, s>>>(A1, XS, AGG3, K1); }
    k_fin_score<<<GR4(K1), TB, 0, s>>>(AGG3, XW, DEG1, nullptr, bu0, HUP, K1, 1, nullptr, nullptr);

    // up to level 0 (final, no activation)
    k_linup16<<<(NN + 15) / 16, TB, 0, s>>>(H0, HUP, MAP1, Wu1, COLCNT, XW, XS);
    k_scatter4<<<GR(EE * 4), TB, 0, s>>>(ei, XS, AGGF, 4);
    k_fin16<<<(NN + 15) / 16, TB, 0, s>>>(AGGF, XW, COLCNT, bu1, out);

    #undef GR
    #undef GR4
}

// round 9
// speedup vs baseline: 1.9777x; 1.6742x over previous
#include <cuda_runtime.h>
#include <math.h>
#include <limits.h>

#define NN 3000
#define EE 48000
#define K1 1500
#define K2 750
#define KWP 384      // padded packed-word K dim (1500/4 = 375 -> 384)
#define NP2 768      // padded K2 for packed operands

// ---------------- device memory pools ----------------
// Zeroed-every-replay region (single memset)
static const size_t Z_A1   = 0;                      // 1500*1500
static const size_t Z_AGG1 = Z_A1   + 2250000;       // 1500*64
static const size_t Z_AGG2 = Z_AGG1 + 96000;         // 750*64
static const size_t Z_AGG3 = Z_AGG2 + 48000;         // 1500*64
static const size_t Z_DEG1 = Z_AGG3 + 96000;         // 1504
static const size_t Z_DEG2 = Z_DEG1 + 1504;          // 752
static const size_t ZTOT   = Z_DEG2 + 752;
// Non-zeroed scratch
static const size_t F_A2   = ZTOT;                   // 750*750
static const size_t F_XW   = F_A2   + 562500;        // 3000*64
static const size_t F_XS   = F_XW   + 192000;        // 3000*64
static const size_t F_H0   = F_XS   + 192000;        // 3000*64
static const size_t F_H1   = F_H0   + 192000;        // 1500*64
static const size_t F_H2   = F_H1   + 96000;         // 750*64
static const size_t F_HUP  = F_H2   + 48000;         // 1500*64
static const size_t F_SC   = F_HUP  + 96000;         // 3008
static const size_t F_TOT  = F_SC   + 3008;

__device__ float g_fpool[F_TOT];

// int pool; first IZTOT zeroed each replay
static const size_t IZ_CNT     = 0;                  // 3000
static const size_t IZ_COLCNT  = 3000;               // 3000
static const size_t IZ_FILL    = 6000;               // 3000
static const size_t IZ_COLFILL = 9000;               // 3000
static const size_t IZTOT      = 12000;
static const size_t I_ROWPTR = 12000;                // 3004
static const size_t I_COLPTR = I_ROWPTR + 3004;      // 3004
static const size_t I_COLS   = I_COLPTR + 3004;      // 48000 (CSR targets)
static const size_t I_CSRC   = I_COLS   + 48000;     // 48000 (CSC sources)
static const size_t I_PERM1  = I_CSRC   + 48000;     // 1504
static const size_t I_PERM2  = I_PERM1  + 1504;      // 768
static const size_t I_MAP1   = I_PERM2  + 768;       // 3000
static const size_t I_MAP2   = I_MAP1   + 3000;      // 1504
static const size_t I_APT    = I_MAP2   + 1504;      // 384*768
static const size_t I_GPT    = I_APT    + (size_t)KWP * NP2;
static const size_t I_TOT    = I_GPT    + (size_t)KWP * NP2;

__device__ int g_ipool[I_TOT];

// ---------------- kernels ----------------

__global__ void k_count(const int* __restrict__ ei, int* cnt, int* colcnt) {
    int e = blockIdx.x * blockDim.x + threadIdx.x;
    if (e >= EE) return;
    atomicAdd(&cnt[ei[e]], 1);
    atomicAdd(&colcnt[ei[EE + e]], 1);
}

// two exclusive scans (CSR rowptr from cnt, CSC colptr from colcnt)
__global__ void k_scan2(const int* __restrict__ cnt, int* rowptr,
                        const int* __restrict__ colcnt, int* colptr) {
    __shared__ int part[1024];
    int tid = threadIdx.x;
    int base = tid * 3;
    for (int rep = 0; rep < 2; rep++) {
        const int* src = rep ? colcnt : cnt;
        int* dst = rep ? colptr : rowptr;
        int l0, l1, l2, sum = 0, v;
        l0 = sum; v = (base + 0 < NN) ? src[base + 0] : 0; sum += v;
        l1 = sum; v = (base + 1 < NN) ? src[base + 1] : 0; sum += v;
        l2 = sum; v = (base + 2 < NN) ? src[base + 2] : 0; sum += v;
        part[tid] = sum;
        __syncthreads();
        for (int off = 1; off < 1024; off <<= 1) {
            int t = (tid >= off) ? part[tid - off] : 0;
            __syncthreads();
            part[tid] += t;
            __syncthreads();
        }
        int offset = (tid > 0) ? part[tid - 1] : 0;
        if (base + 0 < NN) dst[base + 0] = offset + l0;
        if (base + 1 < NN) dst[base + 1] = offset + l1;
        if (base + 2 < NN) dst[base + 2] = offset + l2;
        if (tid == 1023) dst[NN] = part[1023];
        __syncthreads();
    }
}

// fill CSR (by source) and CSC (by target)
__global__ void k_fill(const int* __restrict__ ei, const int* __restrict__ rowptr,
                       const int* __restrict__ colptr, int* fill, int* colfill,
                       int* cols, int* csrc) {
    int e = blockIdx.x * blockDim.x + threadIdx.x;
    if (e >= EE) return;
    int s = ei[e], t = ei[EE + e];
    int p = rowptr[s] + atomicAdd(&fill[s], 1);
    cols[p] = t;
    int q = colptr[t] + atomicAdd(&colfill[t], 1);
    csrc[q] = s;
}

// XW = x(NN x 16) @ W0(16 x 64); XS = XW * rsqrt(colcnt+2)
__global__ void k_lin0(const float* __restrict__ x, const float* __restrict__ W,
                       const int* __restrict__ colcnt, float* __restrict__ XW,
                       float* __restrict__ XS) {
    __shared__ float sh[4][16];
    int tid = threadIdx.x;
    int base = blockIdx.x * 4;
    if (tid < 64) {
        int r = tid >> 4, k = tid & 15;
        int i = base + r;
        sh[r][k] = (i < NN) ? x[i * 16 + k] : 0.f;
    }
    __syncthreads();
    int r = tid >> 6, c = tid & 63;
    int i = base + r;
    if (i >= NN) return;
    float acc = 0.f;
    #pragma unroll
    for (int k = 0; k < 16; k++) acc += sh[r][k] * W[k * 64 + c];
    float di = rsqrtf((float)colcnt[i] + 2.f);
    XW[i * 64 + c] = acc;
    XS[i * 64 + c] = acc * di;
}

// GCN0: CSC gather + finalize + tanh + fused score1 (no atomics)
__global__ void k_gcn0(const int* __restrict__ colptr, const int* __restrict__ csrc,
                       const float* __restrict__ XS, const float* __restrict__ XW,
                       const int* __restrict__ colcnt, const float* __restrict__ b,
                       float* __restrict__ H, const float* __restrict__ p,
                       float* __restrict__ score) {
    __shared__ float part[8], ppart[8];
    int tid = threadIdx.x;
    int r = tid >> 6, c = tid & 63;
    int i = blockIdx.x * 4 + r;
    float v = 0.f;
    if (i < NN) {
        float acc = 0.f;
        int p0 = colptr[i], p1 = colptr[i + 1];
        for (int q = p0; q < p1; q++) acc += XS[csrc[q] * 64 + c];
        float di = rsqrtf((float)colcnt[i] + 2.f);
        v = tanhf(di * acc + 2.f * di * di * XW[i * 64 + c] + b[c]);
        H[i * 64 + c] = v;
    }
    float pc = p[c];
    float hp = (i < NN) ? v * pc : 0.f;
    float pp = (r == 0) ? pc * pc : 0.f;
    #pragma unroll
    for (int off = 16; off > 0; off >>= 1) {
        hp += __shfl_down_sync(0xffffffffu, hp, off);
        pp += __shfl_down_sync(0xffffffffu, pp, off);
    }
    int w = tid >> 5, lane = tid & 31;
    if (lane == 0) { part[w] = hp; ppart[w] = pp; }
    __syncthreads();
    if (tid < 4) {
        int ii = blockIdx.x * 4 + tid;
        if (ii < NN) {
            float dot = part[tid * 2] + part[tid * 2 + 1];
            float pn = ppart[0] + ppart[1];
            score[ii] = tanhf(dot * rsqrtf(pn));
        }
    }
}

// radix top-k SET selection (positions arbitrary; boundary ties -> lowest index)
__device__ __forceinline__ unsigned f2o(float f) {
    unsigned b = __float_as_uint(f);
    return (b & 0x80000000u) ? ~b : (b | 0x80000000u);
}
__global__ void k_select(const float* __restrict__ score, int n, int k,
                         int* __restrict__ perm, int* __restrict__ map) {
    __shared__ int hist[256];
    __shared__ unsigned sh_prefix;
    __shared__ int sh_rem, eqn, poscnt;
    __shared__ int eqidx[3072];
    int tid = threadIdx.x;
    if (tid == 0) { sh_prefix = 0; sh_rem = k; eqn = 0; poscnt = 0; }
    __syncthreads();
    for (int shift = 24; shift >= 0; shift -= 8) {
        if (tid < 256) hist[tid] = 0;
        __syncthreads();
        unsigned pref = sh_prefix;
        unsigned hmask = (shift < 24) ? (0xFFFFFFFFu << (shift + 8)) : 0u;
        for (int i = tid; i < n; i += blockDim.x) {
            unsigned u = f2o(score[i]);
            if ((u & hmask) == (pref & hmask))
                atomicAdd(&hist[(u >> shift) & 0xFF], 1);
        }
        __syncthreads();
        if (tid == 0) {
            int rem = sh_rem, cum = 0, d = 255;
            for (; d > 0; d--) { if (cum + hist[d] >= rem) break; cum += hist[d]; }
            sh_prefix = pref | ((unsigned)d << shift);
            sh_rem = rem - cum;
        }
        __syncthreads();
    }
    unsigned T = sh_prefix;
    int rem = sh_rem;
    for (int i = tid; i < n; i += blockDim.x) {
        unsigned u = f2o(score[i]);
        if (u > T) {
            int pos = atomicAdd(&poscnt, 1);
            perm[pos] = i; map[i] = pos;
        } else {
            map[i] = -1;
            if (u == T) { int e = atomicAdd(&eqn, 1); eqidx[e] = i; }
        }
    }
    __syncthreads();
    int m = eqn;
    for (int e = tid; e < m; e += blockDim.x) {
        int id = eqidx[e];
        int rank = 0;
        for (int f = 0; f < m; f++) rank += (eqidx[f] < id);
        if (rank < rem) {
            int pos = atomicAdd(&poscnt, 1);
            perm[pos] = id; map[id] = pos;
        }
    }
}

// fused (B@B + 2B)[perm x perm] off-diag (B = offdiag(A0)) + column-degree accumulation
__global__ void k_bb2(const int* __restrict__ ei, const int* __restrict__ rowptr,
                      const int* __restrict__ cols, const int* __restrict__ map,
                      float* A1v, float* deg, int nsub) {
    int e = blockIdx.x * blockDim.x + threadIdx.x;
    if (e >= EE) return;
    int s = ei[e], t = ei[EE + e];
    if (s == t) return;
    int i = map[s];
    if (i < 0) return;
    int j0 = map[t];
    if (j0 >= 0 && j0 != i) {
        atomicAdd(&A1v[(size_t)i * nsub + j0], 2.0f);
        atomicAdd(&deg[j0], 2.0f);
    }
    int p0 = rowptr[t], p1 = rowptr[t + 1];
    for (int p = p0; p < p1; p++) {
        int u = cols[p];
        if (u == t) continue;
        int j = map[u];
        if (j < 0 || j == i) continue;
        atomicAdd(&A1v[(size_t)i * nsub + j], 1.0f);
        atomicAdd(&deg[j], 1.0f);
    }
}

// pooled linear: XW = (H[perm[i]] * sc[perm[i]]) @ W(64x64); XS = XW * rsqrt(deg+2)
__global__ void k_linpool(const float* __restrict__ H, const float* __restrict__ sc,
                          const int* __restrict__ perm, const float* __restrict__ W,
                          const float* __restrict__ deg, float* __restrict__ XW,
                          float* __restrict__ XS, int n) {
    __shared__ float sh[4][64];
    int tid = threadIdx.x;
    int base = blockIdx.x * 4;
    int r = tid >> 6, kc = tid & 63;
    int i = base + r;
    float lv = 0.f;
    if (i < n) { int src = perm[i]; lv = H[(size_t)src * 64 + kc] * sc[src]; }
    sh[r][kc] = lv;
    __syncthreads();
    if (i >= n) return;
    float acc = 0.f;
    #pragma unroll
    for (int k = 0; k < 64; k++) acc += sh[r][k] * W[k * 64 + kc];
    float di = rsqrtf(deg[i] + 2.f);
    XW[i * 64 + kc] = acc;
    XS[i * 64 + kc] = acc * di;
}

// up-path linear: XW = (res + up[map]) @ W(64x64); XS = XW * rsqrt(deg+2)
__global__ void k_linup64(const float* __restrict__ res, const float* __restrict__ up,
                          const int* __restrict__ map, const float* __restrict__ W,
                          const float* __restrict__ deg, float* __restrict__ XW,
                          float* __restrict__ XS, int n) {
    __shared__ float sh[4][64];
    int tid = threadIdx.x;
    int base = blockIdx.x * 4;
    int r = tid >> 6, kc = tid & 63;
    int i = base + r;
    float lv = 0.f;
    if (i < n) {
        int m = map[i];
        lv = res[(size_t)i * 64 + kc] + (m >= 0 ? up[(size_t)m * 64 + kc] : 0.f);
    }
    sh[r][kc] = lv;
    __syncthreads();
    if (i >= n) return;
    float acc = 0.f;
    #pragma unroll
    for (int k = 0; k < 64; k++) acc += sh[r][k] * W[k * 64 + kc];
    float di = rsqrtf(deg[i] + 2.f);
    XW[i * 64 + kc] = acc;
    XS[i * 64 + kc] = acc * di;
}

// final up: XW(16) = (H0 + HUP[map1]) @ Wu1(64x16); XS = XW * rsqrt(colcnt+2)
__global__ void k_linup16(const float* __restrict__ res, const float* __restrict__ up,
                          const int* __restrict__ map, const float* __restrict__ W,
                          const int* __restrict__ colcnt, float* __restrict__ XW,
                          float* __restrict__ XS) {
    __shared__ float sh[16][64];
    int tid = threadIdx.x;
    int base = blockIdx.x * 16;
    #pragma unroll
    for (int q = 0; q < 4; q++) {
        int li = tid + q * 256;
        int r = li >> 6, k = li & 63;
        int i = base + r;
        float lv = 0.f;
        if (i < NN) {
            int m = map[i];
            lv = res[(size_t)i * 64 + k] + (m >= 0 ? up[(size_t)m * 64 + k] : 0.f);
        }
        sh[r][k] = lv;
    }
    __syncthreads();
    int r = tid >> 4, c = tid & 15;
    int i = base + r;
    if (i >= NN) return;
    float acc = 0.f;
    #pragma unroll
    for (int k = 0; k < 64; k++) acc += sh[r][k] * W[k * 16 + c];
    float di = rsqrtf((float)colcnt[i] + 2.f);
    XW[i * 16 + c] = acc;
    XS[i * 16 + c] = acc * di;
}

// final GCN: CSC gather (C=16) + finalize, no activation
__global__ void k_gcnF(const int* __restrict__ colptr, const int* __restrict__ csrc,
                       const float* __restrict__ XS, const float* __restrict__ XW,
                       const int* __restrict__ colcnt, const float* __restrict__ b,
                       float* __restrict__ out) {
    int tid = threadIdx.x;
    int r = tid >> 4, c = tid & 15;
    int i = blockIdx.x * 16 + r;
    if (i >= NN) return;
    float acc = 0.f;
    int p0 = colptr[i], p1 = colptr[i + 1];
    for (int q = p0; q < p1; q++) acc += XS[csrc[q] * 16 + c];
    float di = rsqrtf((float)colcnt[i] + 2.f);
    out[i * 16 + c] = di * acc + 2.f * di * di * XW[i * 16 + c] + b[c];
}

// finalize (C=64) + optional score
__global__ void k_fin_score(const float* __restrict__ agg, const float* __restrict__ xw,
                            const float* __restrict__ deg, const float* __restrict__ b,
                            float* __restrict__ out, int n, int act,
                            const float* __restrict__ p, float* score) {
    __shared__ float part[8], ppart[8];
    int tid = threadIdx.x;
    int r = tid >> 6, c = tid & 63;
    int i = blockIdx.x * 4 + r;
    float v = 0.f;
    if (i < n) {
        float di = rsqrtf(deg[i] + 2.f);
        int idx = i * 64 + c;
        v = di * agg[idx] + 2.f * di * di * xw[idx] + b[c];
        if (act) v = tanhf(v);
        out[idx] = v;
    }
    if (p) {
        float pc = p[c];
        float hp = (i < n) ? v * pc : 0.f;
        float pp = (r == 0) ? pc * pc : 0.f;
        #pragma unroll
        for (int off = 16; off > 0; off >>= 1) {
            hp += __shfl_down_sync(0xffffffffu, hp, off);
            pp += __shfl_down_sync(0xffffffffu, pp, off);
        }
        int w = tid >> 5, lane = tid & 31;
        if (lane == 0) { part[w] = hp; ppart[w] = pp; }
        __syncthreads();
        if (tid < 4) {
            int ii = blockIdx.x * 4 + tid;
            if (ii < n) {
                float dot = part[tid * 2] + part[tid * 2 + 1];
                float pn = ppart[0] + ppart[1];
                score[ii] = tanhf(dot * rsqrtf(pn));
            }
        }
    }
}

// out[t,c] += sum_s A[s,t] * X[s,c]   (64 cols; out pre-zeroed; atomic s-split)
__global__ void k_atx(const float* __restrict__ A, const float* __restrict__ X,
                      float* out, int n) {
    __shared__ float As[8][32];
    __shared__ float Xs[8][64];
    int tid = threadIdx.x;
    int c = tid & 63, g = tid >> 6;
    int T0 = blockIdx.x * 32;
    int chunks = gridDim.y;
    int per = (n + chunks - 1) / chunks;
    int s_begin = blockIdx.y * per;
    int s_end = min(s_begin + per, n);
    float acc[8] = {0.f, 0.f, 0.f, 0.f, 0.f, 0.f, 0.f, 0.f};
    for (int s0 = s_begin; s0 < s_end; s0 += 8) {
        {
            int ss = tid >> 5, tt = tid & 31;
            int gs = s0 + ss, gt = T0 + tt;
            As[ss][tt] = (gs < s_end && gt < n) ? A[(size_t)gs * n + gt] : 0.f;
        }
        #pragma unroll
        for (int q = 0; q < 2; q++) {
            int li = tid + q * 256;
            int ss = li >> 6, cc = li & 63;
            int gs = s0 + ss;
            Xs[ss][cc] = (gs < s_end) ? X[(size_t)gs * 64 + cc] : 0.f;
        }
        __syncthreads();
        #pragma unroll
        for (int ss = 0; ss < 8; ss++) {
            float xv = Xs[ss][c];
            #pragma unroll
            for (int k = 0; k < 8; k++) acc[k] += As[ss][g * 8 + k] * xv;
        }
        __syncthreads();
    }
    #pragma unroll
    for (int k = 0; k < 8; k++) {
        int t = T0 + g * 8 + k;
        if (t < n) atomicAdd(&out[(size_t)t * 64 + c], acc[k]);
    }
}

// pack A1 rows (A-side) and columns (B-side) of the A2 GEMM into int8x4 words
__global__ void k_pack(const float* __restrict__ A1v, const int* __restrict__ perm,
                       int* __restrict__ Apt, int* __restrict__ Gpt) {
    int idx = blockIdx.x * blockDim.x + threadIdx.x;
    const int half = KWP * NP2;
    if (idx >= 2 * half) return;
    int sel = (idx >= half) ? 1 : 0;
    int l = idx - sel * half;
    int w = l / NP2, i = l - w * NP2;
    int v = 0;
    if (i < K2) {
        int pi = perm[i];
        if (sel == 0) {
            const float* row = A1v + (size_t)pi * K1;
            #pragma unroll
            for (int q = 0; q < 4; q++) {
                int kq = 4 * w + q;
                int b = (kq < K1) ? (int)row[kq] : 0;
                v |= (b & 0xFF) << (8 * q);
            }
        } else {
            #pragma unroll
            for (int q = 0; q < 4; q++) {
                int kq = 4 * w + q;
                int b = (kq < K1) ? (int)A1v[(size_t)kq * K1 + pi] : 0;
                v |= (b & 0xFF) << (8 * q);
            }
        }
    }
    if (sel == 0) Apt[w * NP2 + i] = v; else Gpt[w * NP2 + i] = v;
}

// A2 = int8 dp4a GEMM (A1[perm,:] @ A1[:,perm]) + 2*A1[pi,pj], diag 0, + col degrees
__global__ void k_dp4aA2(const int* __restrict__ Apt, const int* __restrict__ Gpt,
                         const float* __restrict__ A1v, const int* __restrict__ perm,
                         float* __restrict__ A2, float* deg2) {
    __shared__ int As[8][68], Bs[8][68];
    __shared__ int prs[64], pcs[64];
    __shared__ float csum[64];
    int tid = threadIdx.x;
    int tx = tid & 15, ty = tid >> 4;
    int row0 = blockIdx.y * 64, col0 = blockIdx.x * 64;
    if (tid < 64) { prs[tid] = (row0 + tid < K2) ? perm[row0 + tid] : 0; csum[tid] = 0.f; }
    else if (tid < 128) { int c = tid - 64; pcs[c] = (col0 + c < K2) ? perm[col0 + c] : 0; }
    __syncthreads();
    int acc[4][4] = {};
    for (int k0 = 0; k0 < KWP; k0 += 8) {
        #pragma unroll
        for (int p = 0; p < 2; p++) {
            int li = tid + p * 256;
            int w = li >> 6, c = li & 63;
            As[w][c] = Apt[(k0 + w) * NP2 + row0 + c];
            Bs[w][c] = Gpt[(k0 + w) * NP2 + col0 + c];
        }
        __syncthreads();
        #pragma unroll
        for (int kk = 0; kk < 8; kk++) {
            int4 a4 = *reinterpret_cast<const int4*>(&As[kk][ty * 4]);
            int4 b4 = *reinterpret_cast<const int4*>(&Bs[kk][tx * 4]);
            int a[4] = {a4.x, a4.y, a4.z, a4.w};
            int b[4] = {b4.x, b4.y, b4.z, b4.w};
            #pragma unroll
            for (int i = 0; i < 4; i++)
                #pragma unroll
                for (int j = 0; j < 4; j++)
                    acc[i][j] = __dp4a(a[i], b[j], acc[i][j]);
        }
        __syncthreads();
    }
    float cj[4] = {0.f, 0.f, 0.f, 0.f};
    #pragma unroll
    for (int i2 = 0; i2 < 4; i2++) {
        int gr = row0 + ty * 4 + i2;
        if (gr >= K2) continue;
        int ar = prs[ty * 4 + i2];
        #pragma unroll
        for (int j = 0; j < 4; j++) {
            int gc = col0 + tx * 4 + j;
            if (gc >= K2) continue;
            float val = (gr == gc) ? 0.f
                      : (float)acc[i2][j] + 2.f * A1v[(size_t)ar * K1 + pcs[tx * 4 + j]];
            A2[(size_t)gr * K2 + gc] = val;
            cj[j] += val;
        }
    }
    #pragma unroll
    for (int j = 0; j < 4; j++) atomicAdd(&csum[tx * 4 + j], cj[j]);
    __syncthreads();
    if (tid < 64 && col0 + tid < K2) atomicAdd(&deg2[col0 + tid], csum[tid]);
}

// ---------------- host orchestration ----------------

extern "C" void kernel_launch(void* const* d_in, const int* in_sizes, int n_in,
                              void* d_out, int out_size) {
    float* fp = nullptr; int* ip = nullptr;
    cudaGetSymbolAddress((void**)&fp, g_fpool);
    cudaGetSymbolAddress((void**)&ip, g_ipool);

    const float* x   = (const float*)d_in[0];
    const int*   ei  = (const int*)  d_in[1];
    const float* W0  = (const float*)d_in[2];
    const float* b0  = (const float*)d_in[3];
    const float* W1  = (const float*)d_in[4];
    const float* b1  = (const float*)d_in[5];
    const float* W2  = (const float*)d_in[6];
    const float* b2  = (const float*)d_in[7];
    const float* p1  = (const float*)d_in[8];
    const float* p2  = (const float*)d_in[9];
    const float* Wu0 = (const float*)d_in[10];
    const float* bu0 = (const float*)d_in[11];
    const float* Wu1 = (const float*)d_in[12];
    const float* bu1 = (const float*)d_in[13];
    float* out = (float*)d_out;

    float *A1 = fp + Z_A1, *AGG1 = fp + Z_AGG1, *AGG2 = fp + Z_AGG2,
          *AGG3 = fp + Z_AGG3, *DEG1 = fp + Z_DEG1, *DEG2 = fp + Z_DEG2,
          *A2 = fp + F_A2, *XW = fp + F_XW, *XS = fp + F_XS,
          *H0 = fp + F_H0, *H1 = fp + F_H1, *H2 = fp + F_H2, *HUP = fp + F_HUP,
          *SC = fp + F_SC;
    int *CNT = ip + IZ_CNT, *COLCNT = ip + IZ_COLCNT, *FILL = ip + IZ_FILL,
        *COLFILL = ip + IZ_COLFILL, *ROWPTR = ip + I_ROWPTR, *COLPTR = ip + I_COLPTR,
        *COLS = ip + I_COLS, *CSRC = ip + I_CSRC, *PERM1 = ip + I_PERM1,
        *PERM2 = ip + I_PERM2, *MAP1 = ip + I_MAP1, *MAP2 = ip + I_MAP2,
        *APT = ip + I_APT, *GPT = ip + I_GPT;

    cudaStream_t s = 0;
    const int TB = 256;
    #define GR(n)  (((n) + TB - 1) / TB)
    #define GR4(n) (((n) + 3) / 4)

    cudaMemsetAsync(fp, 0, ZTOT * sizeof(float), s);
    cudaMemsetAsync(ip, 0, IZTOT * sizeof(int), s);

    // CSR + CSC of A0
    k_count<<<GR(EE), TB, 0, s>>>(ei, CNT, COLCNT);
    k_scan2<<<1, 1024, 0, s>>>(CNT, ROWPTR, COLCNT, COLPTR);
    k_fill<<<GR(EE), TB, 0, s>>>(ei, ROWPTR, COLPTR, FILL, COLFILL, COLS, CSRC);

    // GCN0 (CSC gather) + score1
    k_lin0<<<GR4(NN), TB, 0, s>>>(x, W0, COLCNT, XW, XS);
    k_gcn0<<<GR4(NN), TB, 0, s>>>(COLPTR, CSRC, XS, XW, COLCNT, b0, H0, p1, SC);

    // pool 1 + A1 (+ DEG1 fused)
    k_select<<<1, 1024, 0, s>>>(SC, NN, K1, PERM1, MAP1);
    k_bb2<<<GR(EE), TB, 0, s>>>(ei, ROWPTR, COLS, MAP1, A1, DEG1, K1);

    // GCN1 + score2
    k_linpool<<<GR4(K1), TB, 0, s>>>(H0, SC, PERM1, W1, DEG1, XW, XS, K1);
    { dim3 g((K1 + 31) / 32, 8); k_atx<<<g, TB, 0, s>>>(A1, XS, AGG1, K1); }
    k_fin_score<<<GR4(K1), TB, 0, s>>>(AGG1, XW, DEG1, b1, H1, K1, 1, p2, SC);

    // pool 2 + A2 via int8 dp4a GEMM (+ DEG2 fused)
    k_select<<<1, 1024, 0, s>>>(SC, K1, K2, PERM2, MAP2);
    k_pack<<<(2 * KWP * NP2 + TB - 1) / TB, TB, 0, s>>>(A1, PERM2, APT, GPT);
    { dim3 g(12, 12); k_dp4aA2<<<g, TB, 0, s>>>(APT, GPT, A1, PERM2, A2, DEG2); }

    // GCN2
    k_linpool<<<GR4(K2), TB, 0, s>>>(H1, SC, PERM2, W2, DEG2, XW, XS, K2);
    { dim3 g((K2 + 31) / 32, 8); k_atx<<<g, TB, 0, s>>>(A2, XS, AGG2, K2); }
    k_fin_score<<<GR4(K2), TB, 0, s>>>(AGG2, XW, DEG2, b2, H2, K2, 1, nullptr, nullptr);

    // up to level 1
    k_linup64<<<GR4(K1), TB, 0, s>>>(H1, H2, MAP2, Wu0, DEG1, XW, XS, K1);
    { dim3 g((K1 + 31) / 32, 8); k_atx<<<g, TB, 0, s>>>(A1, XS, AGG3, K1); }
    k_fin_score<<<GR4(K1), TB, 0, s>>>(AGG3, XW, DEG1, bu0, HUP, K1, 1, nullptr, nullptr);

    // up to level 0 (final, no activation; CSC gather)
    k_linup16<<<(NN + 15) / 16, TB, 0, s>>>(H0, HUP, MAP1, Wu1, COLCNT, XW, XS);
    k_gcnF<<<(NN + 15) / 16, TB, 0, s>>>(COLPTR, CSRC, XS, XW, COLCNT, bu1, out);

    #undef GR
    #undef GR4
}